// round 1
// baseline (speedup 1.0000x reference)
#include <cuda_runtime.h>
#include <math.h>

#define B_ 64
#define ENC_ 256
#define DEC_ 512
#define ATTN_ 256
#define FMAP_ 512
#define HW_ 256
#define NC2_ 98
#define TSTEPS 31

// ---------------- scratch (__device__ globals; no runtime alloc) ----------------
__device__ float g_Wcat0T[768 * 2048];          // [k][n] k<256:Wih0, else Whh0
__device__ float g_Wcat1T[1024 * 2048];         // [k][n]
__device__ float g_convWT[512 * 9 * 256];       // [c][tap][attn]
__device__ float g_elwT[512 * 256];             // [k][attn]
__device__ float g_fcT[1024 * 98];              // [k][class]
__device__ float g_fmapT[64 * 256 * 512];       // [b][hw][c]
__device__ float g_efmap[64 * 256 * 256];       // [b][attn][hw]
__device__ float g_xh0[64 * 768];               // [b][emb(256)|h0(512)]
__device__ float g_xh1[64 * 1024];              // [b][h0new(512)|h1(512)]
__device__ float g_c0s[64 * 512];
__device__ float g_c1s[64 * 512];
__device__ float g_part[8 * 64 * 2048];         // K-split GEMM partials

__device__ __forceinline__ float sigf(float x) { return 1.0f / (1.0f + expf(-x)); }

// ---------------- setup: transposes / repacks ----------------
__global__ void k_transpose(const float* __restrict__ Wih0, const float* __restrict__ Whh0,
                            const float* __restrict__ Wih1, const float* __restrict__ Whh1,
                            const float* __restrict__ efw, const float* __restrict__ elw,
                            const float* __restrict__ fcw, const float* __restrict__ fmap) {
    const int y = blockIdx.y;
    const int stride = gridDim.x * blockDim.x;
    const int i0 = blockIdx.x * blockDim.x + threadIdx.x;
    if (y == 0) {
        for (int i = i0; i < 768 * 2048; i += stride) {
            int k = i >> 11, n = i & 2047;
            g_Wcat0T[i] = (k < 256) ? Wih0[n * 256 + k] : Whh0[n * 512 + (k - 256)];
        }
    } else if (y == 1) {
        for (int i = i0; i < 1024 * 2048; i += stride) {
            int k = i >> 11, n = i & 2047;
            g_Wcat1T[i] = (k < 512) ? Wih1[n * 512 + k] : Whh1[n * 512 + (k - 512)];
        }
    } else if (y == 2) {
        for (int i = i0; i < 4608 * 256; i += stride) {
            int ck = i >> 8, a = i & 255;
            g_convWT[i] = efw[a * 4608 + ck];
        }
    } else if (y == 3) {
        for (int i = i0; i < 512 * 256; i += stride) {
            int k = i >> 8, a = i & 255;
            g_elwT[i] = elw[a * 512 + k];
        }
    } else if (y == 4) {
        for (int i = i0; i < 1024 * 98; i += stride) {
            int k = i / 98, j = i % 98;
            g_fcT[i] = fcw[j * 1024 + k];
        }
    } else {
        for (int i = i0; i < 64 * 256 * 512; i += stride) {
            int b = i >> 17, rem = i & 131071;
            int hw = rem >> 9, c = rem & 511;
            g_fmapT[i] = fmap[b * 131072 + c * 256 + hw];
        }
    }
}

// ---------------- init states ----------------
__global__ void k_init(const float* __restrict__ h0, const float* __restrict__ c0,
                       const float* __restrict__ emb) {
    int idx = blockIdx.x * blockDim.x + threadIdx.x;
    const int S0 = 64 * 768, S1 = S0 + 64 * 512, S2 = S1 + 64 * 512, S3 = S2 + 64 * 512;
    if (idx < S0) {
        int b = idx / 768, k = idx % 768;
        g_xh0[idx] = (k < 256) ? emb[k] : h0[b * 512 + (k - 256)];   // BOS label 0
    } else if (idx < S1) {
        int r = idx - S0; int b = r >> 9, d = r & 511;
        g_xh1[b * 1024 + 512 + d] = h0[32768 + b * 512 + d];          // layer-1 init h
    } else if (idx < S2) {
        int r = idx - S1;
        g_c0s[r] = c0[r];
    } else if (idx < S3) {
        int r = idx - S2;
        g_c1s[r] = c0[32768 + r];
    }
}

// ---------------- 3x3 conv (implicit GEMM, fp32) ----------------
__global__ void k_conv(const float* __restrict__ fmap, const float* __restrict__ efb) {
    __shared__ float xs[8][4][34];
    __shared__ float ws[8][9][64];
    const int b = blockIdx.z;
    const int s0row = blockIdx.y * 2;   // 2 output rows per block
    const int n0 = blockIdx.x * 64;
    const int tid = threadIdx.x;
    const int tx = tid & 15, ty = tid >> 4;
    const int orow = tx >> 3;
    const int w0 = (tx & 7) * 4;
    const int a0 = ty * 4;
    float acc[4][4] = {};
    const float* fb = fmap + b * (512 * 256);

    for (int cc = 0; cc < 512; cc += 8) {
        for (int i = tid; i < 8 * 4 * 34; i += 256) {
            int c = i / 136, rem = i % 136, ri = rem / 34, wi = rem % 34;
            int row = s0row - 1 + ri, w = wi - 1;
            float v = 0.0f;
            if (row >= 0 && row < 8 && w >= 0 && w < 32)
                v = fb[(cc + c) * 256 + row * 32 + w];
            ((float*)xs)[i] = v;
        }
        for (int i = tid; i < 8 * 9 * 64; i += 256) {
            int c = i / 576, rem = i % 576, tap = rem / 64, a = rem % 64;
            ((float*)ws)[i] = g_convWT[((cc + c) * 9 + tap) * 256 + n0 + a];
        }
        __syncthreads();
#pragma unroll
        for (int c = 0; c < 8; c++) {
#pragma unroll
            for (int dy = 0; dy < 3; dy++) {
                float xw[6];
#pragma unroll
                for (int j = 0; j < 6; j++) xw[j] = xs[c][orow + dy][w0 + j];
#pragma unroll
                for (int dx = 0; dx < 3; dx++) {
                    float4 wv = *(const float4*)&ws[c][dy * 3 + dx][a0];
#pragma unroll
                    for (int j = 0; j < 4; j++) {
                        acc[j][0] += xw[j + dx] * wv.x;
                        acc[j][1] += xw[j + dx] * wv.y;
                        acc[j][2] += xw[j + dx] * wv.z;
                        acc[j][3] += xw[j + dx] * wv.w;
                    }
                }
            }
        }
        __syncthreads();
    }
    float* eb = g_efmap + b * 65536;
    const int s = (s0row + orow) * 32 + w0;
#pragma unroll
    for (int ai = 0; ai < 4; ai++) {
        int a = n0 + a0 + ai;
        float bias = efb[a];
        float4 v = make_float4(acc[0][ai] + bias, acc[1][ai] + bias,
                               acc[2][ai] + bias, acc[3][ai] + bias);
        *(float4*)&eb[a * 256 + s] = v;
    }
}

// ---------------- K-split SGEMM: gates partials [ks][64][2048] ----------------
__global__ void k_gemm(int which) {
    const float* __restrict__ A  = which ? g_xh1 : g_xh0;
    const float* __restrict__ Bt = which ? g_Wcat1T : g_Wcat0T;
    const int K = which ? 1024 : 768;
    const int n0 = blockIdx.x * 64;
    const int k0 = blockIdx.y * 128;
    __shared__ float As[16][68];
    __shared__ float Bs[16][64];
    const int tid = threadIdx.x;
    const int tm4 = (tid & 15) * 4;
    const int tn4 = (tid >> 4) * 4;
    float acc[4][4] = {};
    for (int kt = k0; kt < k0 + 128; kt += 16) {
#pragma unroll
        for (int p = 0; p < 4; p++) {
            int m = (tid >> 4) + p * 16;
            int kk = tid & 15;
            As[kk][m] = A[m * K + kt + kk];
        }
#pragma unroll
        for (int p = 0; p < 4; p++) {
            int kk = (tid >> 6) + p * 4;
            int n = tid & 63;
            Bs[kk][n] = Bt[(kt + kk) * 2048 + n0 + n];
        }
        __syncthreads();
#pragma unroll
        for (int kk = 0; kk < 16; kk++) {
            float4 av = *(const float4*)&As[kk][tm4];
            float4 bv = *(const float4*)&Bs[kk][tn4];
            float a_[4] = {av.x, av.y, av.z, av.w};
            float b_[4] = {bv.x, bv.y, bv.z, bv.w};
#pragma unroll
            for (int i = 0; i < 4; i++)
#pragma unroll
                for (int j = 0; j < 4; j++) acc[i][j] += a_[i] * b_[j];
        }
        __syncthreads();
    }
    float* P = g_part + blockIdx.y * (64 * 2048);
#pragma unroll
    for (int i = 0; i < 4; i++) {
        float4 v = make_float4(acc[i][0], acc[i][1], acc[i][2], acc[i][3]);
        *(float4*)&P[(tm4 + i) * 2048 + n0 + tn4] = v;
    }
}

// ---------------- LSTM layer-0 pointwise + next-step input prep ----------------
__global__ void k_point0(const float* __restrict__ bih, const float* __restrict__ bhh,
                         const int* __restrict__ target, const float* __restrict__ emb, int t) {
    const int idx = blockIdx.x * blockDim.x + threadIdx.x;  // 64*512
    const int b = idx >> 9, d = idx & 511;
    float gi = 0, gf = 0, gg = 0, go = 0;
#pragma unroll
    for (int ks = 0; ks < 6; ks++) {
        const float* p = g_part + ks * (64 * 2048) + b * 2048;
        gi += p[d]; gf += p[512 + d]; gg += p[1024 + d]; go += p[1536 + d];
    }
    gi += bih[d] + bhh[d];
    gf += bih[512 + d] + bhh[512 + d];
    gg += bih[1024 + d] + bhh[1024 + d];
    go += bih[1536 + d] + bhh[1536 + d];
    float c = g_c0s[idx];
    c = sigf(gf) * c + sigf(gi) * tanhf(gg);
    float h = sigf(go) * tanhf(c);
    g_c0s[idx] = c;
    g_xh1[b * 1024 + d] = h;          // LSTM1 input, this step
    g_xh0[b * 768 + 256 + d] = h;     // recurrent input, next step
    if (d < 256 && t < 30) {
        int lab = target[b * 30 + t];  // label_{t+1} = target[:, t]
        g_xh0[b * 768 + d] = emb[lab * 256 + d];
    }
}

// ---------------- fused: LSTM1 pointwise + attention + glimpse + fc ----------------
__global__ void k_attn(const float* __restrict__ bih, const float* __restrict__ bhh,
                       const float* __restrict__ elb, const float* __restrict__ aw,
                       const float* __restrict__ ab, const float* __restrict__ fcb,
                       float* __restrict__ out, int t) {
    const int b = blockIdx.x;
    const int tid = threadIdx.x;  // 256
    __shared__ float hs[512], ehs[256], aws[256], ps[256], gs[512];
    __shared__ float red[8], red2[8], fin[2];
    __shared__ float facc[2][98];

    // LSTM layer-1 pointwise (row b only)
#pragma unroll
    for (int r = 0; r < 2; r++) {
        int d = tid + r * 256;
        float gi = 0, gf = 0, gg = 0, go = 0;
#pragma unroll
        for (int ks = 0; ks < 8; ks++) {
            const float* p = g_part + ks * (64 * 2048) + b * 2048;
            gi += p[d]; gf += p[512 + d]; gg += p[1024 + d]; go += p[1536 + d];
        }
        gi += bih[d] + bhh[d];
        gf += bih[512 + d] + bhh[512 + d];
        gg += bih[1024 + d] + bhh[1024 + d];
        go += bih[1536 + d] + bhh[1536 + d];
        float c = g_c1s[b * 512 + d];
        c = sigf(gf) * c + sigf(gi) * tanhf(gg);
        float h = sigf(go) * tanhf(c);
        g_c1s[b * 512 + d] = c;
        g_xh1[b * 1024 + 512 + d] = h;   // recurrent input, next step
        hs[d] = h;
    }
    aws[tid] = aw[tid];
    __syncthreads();

    // e_h = h1 @ e_lstm_w^T + b
    {
        float acc = elb[tid];
        const float* w = g_elwT + tid;
#pragma unroll 8
        for (int k = 0; k < 512; k++) acc += hs[k] * w[k * 256];
        ehs[tid] = acc;
    }
    __syncthreads();

    // scores + softmax
    float sc = ab[0];
    {
        const float* ef = g_efmap + b * 65536 + tid;
#pragma unroll 4
        for (int a = 0; a < 256; a++) sc += aws[a] * tanhf(ehs[a] + ef[a * 256]);
    }
    const int warp = tid >> 5, lane = tid & 31;
    float m = sc;
#pragma unroll
    for (int o = 16; o; o >>= 1) m = fmaxf(m, __shfl_xor_sync(0xffffffffu, m, o));
    if (lane == 0) red[warp] = m;
    __syncthreads();
    if (tid == 0) {
        float v = red[0];
#pragma unroll
        for (int i = 1; i < 8; i++) v = fmaxf(v, red[i]);
        fin[0] = v;
    }
    __syncthreads();
    float e = expf(sc - fin[0]);
    float s = e;
#pragma unroll
    for (int o = 16; o; o >>= 1) s += __shfl_xor_sync(0xffffffffu, s, o);
    if (lane == 0) red2[warp] = s;
    __syncthreads();
    if (tid == 0) {
        float v = 0;
#pragma unroll
        for (int i = 0; i < 8; i++) v += red2[i];
        fin[1] = v;
    }
    __syncthreads();
    float p = e / fin[1];
    ps[tid] = p;
    out[194432 + (b * 31 + t) * 256 + tid] = p;    // masks
    __syncthreads();

    // glimpse = fmap @ mask (coalesced via fmapT)
#pragma unroll
    for (int r = 0; r < 2; r++) {
        int c = tid + r * 256;
        float g = 0;
        const float* ft = g_fmapT + b * 131072 + c;
#pragma unroll 8
        for (int hw = 0; hw < 256; hw++) g += ft[hw * 512] * ps[hw];
        gs[c] = g;
        out[702336 + (b * 31 + t) * 512 + c] = g;  // glimpses
    }
    __syncthreads();

    // fc logits
    if (tid < 196) {
        int half = (tid >= 98) ? 1 : 0;
        int j = tid - half * 98;
        const float* src = half ? gs : hs;
        const float* w = g_fcT + half * (512 * 98) + j;
        float acc = 0;
#pragma unroll 8
        for (int k = 0; k < 512; k++) acc += src[k] * w[k * 98];
        facc[half][j] = acc;
    }
    __syncthreads();
    if (tid < 98)
        out[(b * 31 + t) * 98 + tid] = facc[0][tid] + facc[1][tid] + fcb[tid];  // logits
}

// ---------------- launch ----------------
extern "C" void kernel_launch(void* const* d_in, const int* in_sizes, int n_in,
                              void* d_out, int out_size) {
    const float* fmap   = (const float*)d_in[0];
    const float* h0     = (const float*)d_in[1];
    const float* c0     = (const float*)d_in[2];
    const int*   target = (const int*)d_in[3];
    const float* emb    = (const float*)d_in[5];
    const float* Wih0   = (const float*)d_in[6];
    const float* Whh0   = (const float*)d_in[7];
    const float* bih0   = (const float*)d_in[8];
    const float* bhh0   = (const float*)d_in[9];
    const float* Wih1   = (const float*)d_in[10];
    const float* Whh1   = (const float*)d_in[11];
    const float* bih1   = (const float*)d_in[12];
    const float* bhh1   = (const float*)d_in[13];
    const float* elw    = (const float*)d_in[14];
    const float* elb    = (const float*)d_in[15];
    const float* efw    = (const float*)d_in[16];
    const float* efb    = (const float*)d_in[17];
    const float* aw     = (const float*)d_in[18];
    const float* ab     = (const float*)d_in[19];
    const float* fcw    = (const float*)d_in[20];
    const float* fcb    = (const float*)d_in[21];
    float* out = (float*)d_out;

    k_transpose<<<dim3(512, 6), 256>>>(Wih0, Whh0, Wih1, Whh1, efw, elw, fcw, fmap);
    k_conv<<<dim3(4, 4, 64), 256>>>(fmap, efb);
    k_init<<<(64 * 2304 + 255) / 256, 256>>>(h0, c0, emb);
    for (int t = 0; t < TSTEPS; t++) {
        k_gemm<<<dim3(32, 6), 256>>>(0);
        k_point0<<<128, 256>>>(bih0, bhh0, target, emb, t);
        k_gemm<<<dim3(32, 8), 256>>>(1);
        k_attn<<<64, 256>>>(bih1, bhh1, elb, aw, ab, fcb, out, t);
    }
}